// round 15
// baseline (speedup 1.0000x reference)
#include <cuda_runtime.h>

#define THREADS 512
#define ROWS_PER_BLOCK 64
#define INV_SQRT3 0.57735026918962576451f

// smem float offsets
//   A    [64 rows][32 upair][12]      : 0     .. 24576   (reused as output staging [64][256])
//   Wq   [4 arrays][32 upair][32 c]x4 : 24576 .. 40960
//   sc   [64 rows][4]                 : 40960 .. 41216
//   bias [64]                         : 41216 .. 41280
#define A_OFF    0
#define W_OFF    24576
#define SC_OFF   40960
#define BIAS_OFF 41216
#define SMEM_FLOATS 41280
#define SMEM_BYTES  (SMEM_FLOATS * 4)

typedef unsigned long long ull;

__device__ __forceinline__ ull fma2(ull a, ull b, ull c) {
    ull d;
    asm("fma.rn.f32x2 %0, %1, %2, %3;" : "=l"(d) : "l"(a), "l"(b), "l"(c));
    return d;
}

__device__ __forceinline__ float red2(ull a) {
    float lo, hi;
    asm("mov.b64 {%0,%1}, %2;" : "=f"(lo), "=f"(hi) : "l"(a));
    return lo + hi;
}

__global__ __launch_bounds__(THREADS, 1)
void o3tp_kernel(const float* __restrict__ in1, const float* __restrict__ in2,
                 const float* __restrict__ Wss, const float* __restrict__ Wvv,
                 const float* __restrict__ Wsv, const float* __restrict__ Wvs,
                 const float* __restrict__ bias, float* __restrict__ out, int n)
{
    extern __shared__ float smem[];
    float* A   = smem + A_OFF;
    float* Wq  = smem + W_OFF;
    float* sc  = smem + SC_OFF;
    float* bsm = smem + BIAS_OFF;

    const int tid  = threadIdx.x;
    const int row0 = blockIdx.x * ROWS_PER_BLOCK;

    // --- per-row scalars (s2, v2) and bias ---
    if (tid < 256) {
        int r  = tid >> 2;
        int gr = min(row0 + r, n - 1);
        sc[tid] = in2[gr * 4 + (tid & 3)];
    }
    if (tid < 64) bsm[tid] = bias[tid];

    // --- pack weights into u-paired float4 arrays ---
    // Wq array a (0..3), each [32 upair][32 lane] of float4:
    //   a=0: col lane      : (ss_u0, ss_u1, vv_u0, vv_u1)
    //   a=1: col lane      : (sv_u0, sv_u1, vs_u0, vs_u1)
    //   a=2: col lane+32   : (ss, ss, vv, vv)
    //   a=3: col lane+32   : (sv, sv, vs, vs)
    {
        float4* w4 = (float4*)Wq;
        for (int idx = tid; idx < 2048; idx += THREADS) {
            int up = idx >> 6;
            int c  = idx & 63;
            int u0 = up * 2, u1 = u0 + 1;
            int half = c >> 5;
            int cc   = c & 31;
            w4[(half * 2 + 0) * 1024 + up * 32 + cc] =
                make_float4(Wss[u0 * 64 + c], Wss[u1 * 64 + c],
                            Wvv[u0 * 64 + c], Wvv[u1 * 64 + c]);
            w4[(half * 2 + 1) * 1024 + up * 32 + cc] =
                make_float4(Wsv[u0 * 64 + c], Wsv[u1 * 64 + c],
                            Wvs[u0 * 64 + c], Wvs[u1 * 64 + c]);
        }
    }
    __syncthreads();   // sc visible for A-pack

    // --- pack per-row inputs, u-paired:
    // A[r][up][12] = { s1s2_u0, s1s2_u1, vvs_u0, vvs_u1, s1_u0, s1_u1,
    //                  vx_u0, vx_u1, vy_u0, vy_u1, vz_u0, vz_u1 }
    for (int idx = tid; idx < 64 * 64; idx += THREADS) {
        int r  = idx >> 6;
        int u  = idx & 63;
        int gr = min(row0 + r, n - 1);
        const float* rowp = in1 + (long)gr * 256;
        float s1 = rowp[u];
        float vx = rowp[64 + 3 * u + 0];
        float vy = rowp[64 + 3 * u + 1];
        float vz = rowp[64 + 3 * u + 2];
        float s2  = sc[r * 4 + 0];
        float v2x = sc[r * 4 + 1];
        float v2y = sc[r * 4 + 2];
        float v2z = sc[r * 4 + 3];
        float vvs = (vx * v2x + vy * v2y + vz * v2z) * INV_SQRT3;
        float* ap = A + r * 384 + (u >> 1) * 12 + (u & 1);
        ap[0]  = s1 * s2;
        ap[2]  = vvs;
        ap[4]  = s1;
        ap[6]  = vx;
        ap[8]  = vy;
        ap[10] = vz;
    }
    __syncthreads();

    // --- main loop: warp owns rows 4w..4w+3; lane owns cols (lane, lane+32) ---
    const int lane  = tid & 31;
    const int wrp   = tid >> 5;
    const int rbase = wrp * 4;

    // acc[r][k]: k = 2*type + half; types: 0=s, 1=sv, 2=vsx, 3=vsy, 4=vsz
    ull acc[4][10];
    #pragma unroll
    for (int r = 0; r < 4; r++)
        #pragma unroll
        for (int k = 0; k < 10; k++) acc[r][k] = 0ull;

    const ulonglong2* Bp = (const ulonglong2*)Wq;

    #pragma unroll 1
    for (int up = 0; up < 32; up++) {
        ulonglong2 q0l = Bp[0 * 1024 + up * 32 + lane];   // .x=ss2 .y=vv2 (col lo)
        ulonglong2 q1l = Bp[1 * 1024 + up * 32 + lane];   // .x=sv2 .y=vs2
        ulonglong2 q0h = Bp[2 * 1024 + up * 32 + lane];   // col hi
        ulonglong2 q1h = Bp[3 * 1024 + up * 32 + lane];
        #pragma unroll
        for (int r = 0; r < 4; r++) {
            const ulonglong2* ap =
                (const ulonglong2*)(A + (rbase + r) * 384 + up * 12);
            ulonglong2 a0 = ap[0];   // .x=s1s2  .y=vvs
            ulonglong2 a1 = ap[1];   // .x=s1    .y=vx
            ulonglong2 a2 = ap[2];   // .x=vy    .y=vz
            acc[r][0] = fma2(a0.x, q0l.x, acc[r][0]);
            acc[r][0] = fma2(a0.y, q0l.y, acc[r][0]);
            acc[r][2] = fma2(a1.x, q1l.x, acc[r][2]);
            acc[r][4] = fma2(a1.y, q1l.y, acc[r][4]);
            acc[r][6] = fma2(a2.x, q1l.y, acc[r][6]);
            acc[r][8] = fma2(a2.y, q1l.y, acc[r][8]);
            acc[r][1] = fma2(a0.x, q0h.x, acc[r][1]);
            acc[r][1] = fma2(a0.y, q0h.y, acc[r][1]);
            acc[r][3] = fma2(a1.x, q1h.x, acc[r][3]);
            acc[r][5] = fma2(a1.y, q1h.y, acc[r][5]);
            acc[r][7] = fma2(a2.x, q1h.y, acc[r][7]);
            acc[r][9] = fma2(a2.y, q1h.y, acc[r][9]);
        }
    }

    __syncthreads();   // all warps done reading A -> reuse as output staging

    // --- epilogue: combine and stage into smem [64 rows][256 cols] ---
    float* stile = smem;
    #pragma unroll
    for (int r = 0; r < 4; r++) {
        int lr = rbase + r;
        float s2  = sc[lr * 4 + 0];
        float v2x = sc[lr * 4 + 1];
        float v2y = sc[lr * 4 + 2];
        float v2z = sc[lr * 4 + 3];
        float* o = stile + lr * 256;
        #pragma unroll
        for (int j = 0; j < 2; j++) {
            int w = lane + 32 * j;
            float s  = red2(acc[r][0 + j]);
            float sv = red2(acc[r][2 + j]);
            float tx = red2(acc[r][4 + j]);
            float ty = red2(acc[r][6 + j]);
            float tz = red2(acc[r][8 + j]);
            o[w] = s + bsm[w];
            o[64 + 3 * w + 0] = sv * v2x + tx * s2;
            o[64 + 3 * w + 1] = sv * v2y + ty * s2;
            o[64 + 3 * w + 2] = sv * v2z + tz * s2;
        }
    }
    __syncthreads();

    // --- coalesced float4 store ---
    const float4* st4 = (const float4*)stile;
    float4* out4 = (float4*)(out + (long)row0 * 256);
    int rows_here = min(ROWS_PER_BLOCK, n - row0);
    int nfl4 = rows_here * 64;
    for (int idx = tid; idx < nfl4; idx += THREADS)
        out4[idx] = st4[idx];
}

extern "C" void kernel_launch(void* const* d_in, const int* in_sizes, int n_in,
                              void* d_out, int out_size) {
    const float* in1  = (const float*)d_in[0];
    const float* in2  = (const float*)d_in[1];
    const float* Wss  = (const float*)d_in[2];
    const float* Wvv  = (const float*)d_in[3];
    const float* Wsv  = (const float*)d_in[4];
    const float* Wvs  = (const float*)d_in[5];
    const float* bias = (const float*)d_in[6];
    float* out = (float*)d_out;

    int n = in_sizes[0] / 256;   // rows

    cudaFuncSetAttribute(o3tp_kernel, cudaFuncAttributeMaxDynamicSharedMemorySize, SMEM_BYTES);

    int blocks = (n + ROWS_PER_BLOCK - 1) / ROWS_PER_BLOCK;
    o3tp_kernel<<<blocks, THREADS, SMEM_BYTES>>>(in1, in2, Wss, Wvv, Wsv, Wvs, bias, out, n);
}

// round 16
// speedup vs baseline: 1.0343x; 1.0343x over previous
#include <cuda_runtime.h>

#define THREADS 512
#define ROWS_PER_BLOCK 64
#define INV_SQRT3 0.57735026918962576451f

// smem float offsets
//   A    [64 rows][32 upair][12]      : 0     .. 24576   (reused as output staging [64][256])
//   Wq   [4 arrays][32 upair][32 c]x4 : 24576 .. 40960
//   sc   [64 rows][4]                 : 40960 .. 41216
//   bias [64]                         : 41216 .. 41280
#define A_OFF    0
#define W_OFF    24576
#define SC_OFF   40960
#define BIAS_OFF 41216
#define SMEM_FLOATS 41280
#define SMEM_BYTES  (SMEM_FLOATS * 4)

typedef unsigned long long ull;

__device__ __forceinline__ ull fma2(ull a, ull b, ull c) {
    ull d;
    asm("fma.rn.f32x2 %0, %1, %2, %3;" : "=l"(d) : "l"(a), "l"(b), "l"(c));
    return d;
}

__device__ __forceinline__ float red2(ull a) {
    float lo, hi;
    asm("mov.b64 {%0,%1}, %2;" : "=f"(lo), "=f"(hi) : "l"(a));
    return lo + hi;
}

__global__ __launch_bounds__(THREADS, 1)
void o3tp_kernel(const float* __restrict__ in1, const float* __restrict__ in2,
                 const float* __restrict__ Wss, const float* __restrict__ Wvv,
                 const float* __restrict__ Wsv, const float* __restrict__ Wvs,
                 const float* __restrict__ bias, float* __restrict__ out, int n)
{
    extern __shared__ float smem[];
    float* A   = smem + A_OFF;
    float* Wq  = smem + W_OFF;
    float* sc  = smem + SC_OFF;
    float* bsm = smem + BIAS_OFF;

    const int tid  = threadIdx.x;
    const int row0 = blockIdx.x * ROWS_PER_BLOCK;

    // --- per-row scalars (s2, v2) and bias ---
    if (tid < 256) {
        int r  = tid >> 2;
        int gr = min(row0 + r, n - 1);
        sc[tid] = in2[gr * 4 + (tid & 3)];
    }
    if (tid < 64) bsm[tid] = bias[tid];

    // --- pack weights into u-paired float4 arrays ---
    // Wq array a (0..3), each [32 upair][32 lane] of float4:
    //   a=0: col lane      : (ss_u0, ss_u1, vv_u0, vv_u1)
    //   a=1: col lane      : (sv_u0, sv_u1, vs_u0, vs_u1)
    //   a=2: col lane+32   : (ss, ss, vv, vv)
    //   a=3: col lane+32   : (sv, sv, vs, vs)
    {
        float4* w4 = (float4*)Wq;
        for (int idx = tid; idx < 2048; idx += THREADS) {
            int up = idx >> 6;
            int c  = idx & 63;
            int u0 = up * 2, u1 = u0 + 1;
            int half = c >> 5;
            int cc   = c & 31;
            w4[(half * 2 + 0) * 1024 + up * 32 + cc] =
                make_float4(Wss[u0 * 64 + c], Wss[u1 * 64 + c],
                            Wvv[u0 * 64 + c], Wvv[u1 * 64 + c]);
            w4[(half * 2 + 1) * 1024 + up * 32 + cc] =
                make_float4(Wsv[u0 * 64 + c], Wsv[u1 * 64 + c],
                            Wvs[u0 * 64 + c], Wvs[u1 * 64 + c]);
        }
    }
    __syncthreads();   // sc visible for A-pack

    // --- pack per-row inputs, u-paired:
    // A[r][up][12] = { s1s2_u0, s1s2_u1, vvs_u0, vvs_u1, s1_u0, s1_u1,
    //                  vx_u0, vx_u1, vy_u0, vy_u1, vz_u0, vz_u1 }
    for (int idx = tid; idx < 64 * 64; idx += THREADS) {
        int r  = idx >> 6;
        int u  = idx & 63;
        int gr = min(row0 + r, n - 1);
        const float* rowp = in1 + (long)gr * 256;
        float s1 = rowp[u];
        float vx = rowp[64 + 3 * u + 0];
        float vy = rowp[64 + 3 * u + 1];
        float vz = rowp[64 + 3 * u + 2];
        float s2  = sc[r * 4 + 0];
        float v2x = sc[r * 4 + 1];
        float v2y = sc[r * 4 + 2];
        float v2z = sc[r * 4 + 3];
        float vvs = (vx * v2x + vy * v2y + vz * v2z) * INV_SQRT3;
        float* ap = A + r * 384 + (u >> 1) * 12 + (u & 1);
        ap[0]  = s1 * s2;
        ap[2]  = vvs;
        ap[4]  = s1;
        ap[6]  = vx;
        ap[8]  = vy;
        ap[10] = vz;
    }
    __syncthreads();

    // --- main loop: warp owns rows 4w..4w+3; lane owns cols (lane, lane+32) ---
    const int lane  = tid & 31;
    const int wrp   = tid >> 5;
    const int rbase = wrp * 4;

    // acc[r][k]: k = 2*type + half; types: 0=s, 1=sv, 2=vsx, 3=vsy, 4=vsz
    ull acc[4][10];
    #pragma unroll
    for (int r = 0; r < 4; r++)
        #pragma unroll
        for (int k = 0; k < 10; k++) acc[r][k] = 0ull;

    const ulonglong2* Bp = (const ulonglong2*)Wq;

    #pragma unroll 1
    for (int up = 0; up < 32; up++) {
        ulonglong2 q0l = Bp[0 * 1024 + up * 32 + lane];   // .x=ss2 .y=vv2 (col lo)
        ulonglong2 q1l = Bp[1 * 1024 + up * 32 + lane];   // .x=sv2 .y=vs2
        ulonglong2 q0h = Bp[2 * 1024 + up * 32 + lane];   // col hi
        ulonglong2 q1h = Bp[3 * 1024 + up * 32 + lane];
        #pragma unroll
        for (int r = 0; r < 4; r++) {
            const ulonglong2* ap =
                (const ulonglong2*)(A + (rbase + r) * 384 + up * 12);
            ulonglong2 a0 = ap[0];   // .x=s1s2  .y=vvs
            ulonglong2 a1 = ap[1];   // .x=s1    .y=vx
            ulonglong2 a2 = ap[2];   // .x=vy    .y=vz
            acc[r][0] = fma2(a0.x, q0l.x, acc[r][0]);
            acc[r][0] = fma2(a0.y, q0l.y, acc[r][0]);
            acc[r][2] = fma2(a1.x, q1l.x, acc[r][2]);
            acc[r][4] = fma2(a1.y, q1l.y, acc[r][4]);
            acc[r][6] = fma2(a2.x, q1l.y, acc[r][6]);
            acc[r][8] = fma2(a2.y, q1l.y, acc[r][8]);
            acc[r][1] = fma2(a0.x, q0h.x, acc[r][1]);
            acc[r][1] = fma2(a0.y, q0h.y, acc[r][1]);
            acc[r][3] = fma2(a1.x, q1h.x, acc[r][3]);
            acc[r][5] = fma2(a1.y, q1h.y, acc[r][5]);
            acc[r][7] = fma2(a2.x, q1h.y, acc[r][7]);
            acc[r][9] = fma2(a2.y, q1h.y, acc[r][9]);
        }
    }

    __syncthreads();   // all warps done reading A -> reuse as output staging

    // --- epilogue: combine and stage into smem [64 rows][256 cols] ---
    float* stile = smem;
    #pragma unroll
    for (int r = 0; r < 4; r++) {
        int lr = rbase + r;
        float s2  = sc[lr * 4 + 0];
        float v2x = sc[lr * 4 + 1];
        float v2y = sc[lr * 4 + 2];
        float v2z = sc[lr * 4 + 3];
        float* o = stile + lr * 256;
        #pragma unroll
        for (int j = 0; j < 2; j++) {
            int w = lane + 32 * j;
            float s  = red2(acc[r][0 + j]);
            float sv = red2(acc[r][2 + j]);
            float tx = red2(acc[r][4 + j]);
            float ty = red2(acc[r][6 + j]);
            float tz = red2(acc[r][8 + j]);
            o[w] = s + bsm[w];
            o[64 + 3 * w + 0] = sv * v2x + tx * s2;
            o[64 + 3 * w + 1] = sv * v2y + ty * s2;
            o[64 + 3 * w + 2] = sv * v2z + tz * s2;
        }
    }
    __syncthreads();

    // --- coalesced float4 store ---
    const float4* st4 = (const float4*)stile;
    float4* out4 = (float4*)(out + (long)row0 * 256);
    int rows_here = min(ROWS_PER_BLOCK, n - row0);
    int nfl4 = rows_here * 64;
    for (int idx = tid; idx < nfl4; idx += THREADS)
        out4[idx] = st4[idx];
}

extern "C" void kernel_launch(void* const* d_in, const int* in_sizes, int n_in,
                              void* d_out, int out_size) {
    const float* in1  = (const float*)d_in[0];
    const float* in2  = (const float*)d_in[1];
    const float* Wss  = (const float*)d_in[2];
    const float* Wvv  = (const float*)d_in[3];
    const float* Wsv  = (const float*)d_in[4];
    const float* Wvs  = (const float*)d_in[5];
    const float* bias = (const float*)d_in[6];
    float* out = (float*)d_out;

    int n = in_sizes[0] / 256;   // rows

    cudaFuncSetAttribute(o3tp_kernel, cudaFuncAttributeMaxDynamicSharedMemorySize, SMEM_BYTES);

    int blocks = (n + ROWS_PER_BLOCK - 1) / ROWS_PER_BLOCK;
    o3tp_kernel<<<blocks, THREADS, SMEM_BYTES>>>(in1, in2, Wss, Wvv, Wsv, Wvs, bias, out, n);
}

// round 17
// speedup vs baseline: 1.0406x; 1.0061x over previous
#include <cuda_runtime.h>

#define THREADS 512
#define ROWS_PER_BLOCK 64
#define INV_SQRT3 0.57735026918962576451f

// smem float offsets
//   A    [64 rows][32 upair][12]      : 0     .. 24576   (reused as output staging [64][256])
//   Wq   [4 arrays][32 upair][32 c]x4 : 24576 .. 40960
//   sc   [64 rows][4]                 : 40960 .. 41216
//   bias [64]                         : 41216 .. 41280
#define A_OFF    0
#define W_OFF    24576
#define SC_OFF   40960
#define BIAS_OFF 41216
#define SMEM_FLOATS 41280
#define SMEM_BYTES  (SMEM_FLOATS * 4)

typedef unsigned long long ull;

__device__ __forceinline__ ull fma2(ull a, ull b, ull c) {
    ull d;
    asm("fma.rn.f32x2 %0, %1, %2, %3;" : "=l"(d) : "l"(a), "l"(b), "l"(c));
    return d;
}

__device__ __forceinline__ float red2(ull a) {
    float lo, hi;
    asm("mov.b64 {%0,%1}, %2;" : "=f"(lo), "=f"(hi) : "l"(a));
    return lo + hi;
}

__global__ __launch_bounds__(THREADS, 1)
void o3tp_kernel(const float* __restrict__ in1, const float* __restrict__ in2,
                 const float* __restrict__ Wss, const float* __restrict__ Wvv,
                 const float* __restrict__ Wsv, const float* __restrict__ Wvs,
                 const float* __restrict__ bias, float* __restrict__ out, int n)
{
    extern __shared__ float smem[];
    float* A   = smem + A_OFF;
    float* Wq  = smem + W_OFF;
    float* sc  = smem + SC_OFF;
    float* bsm = smem + BIAS_OFF;

    const int tid  = threadIdx.x;
    const int row0 = blockIdx.x * ROWS_PER_BLOCK;

    // --- per-row scalars (s2, v2) and bias ---
    if (tid < 256) {
        int r  = tid >> 2;
        int gr = min(row0 + r, n - 1);
        sc[tid] = in2[gr * 4 + (tid & 3)];
    }
    if (tid < 64) bsm[tid] = bias[tid];

    // --- pack weights into u-paired float4 arrays ---
    // Wq array a (0..3), each [32 upair][32 lane] of float4:
    //   a=0: col lane      : (ss_u0, ss_u1, vv_u0, vv_u1)
    //   a=1: col lane      : (sv_u0, sv_u1, vs_u0, vs_u1)
    //   a=2: col lane+32   : (ss, ss, vv, vv)
    //   a=3: col lane+32   : (sv, sv, vs, vs)
    {
        float4* w4 = (float4*)Wq;
        for (int idx = tid; idx < 2048; idx += THREADS) {
            int up = idx >> 6;
            int c  = idx & 63;
            int u0 = up * 2, u1 = u0 + 1;
            int half = c >> 5;
            int cc   = c & 31;
            w4[(half * 2 + 0) * 1024 + up * 32 + cc] =
                make_float4(Wss[u0 * 64 + c], Wss[u1 * 64 + c],
                            Wvv[u0 * 64 + c], Wvv[u1 * 64 + c]);
            w4[(half * 2 + 1) * 1024 + up * 32 + cc] =
                make_float4(Wsv[u0 * 64 + c], Wsv[u1 * 64 + c],
                            Wvs[u0 * 64 + c], Wvs[u1 * 64 + c]);
        }
    }
    __syncthreads();   // sc visible for A-pack

    // --- pack per-row inputs, u-paired:
    // A[r][up][12] = { s1s2_u0, s1s2_u1, vvs_u0, vvs_u1, s1_u0, s1_u1,
    //                  vx_u0, vx_u1, vy_u0, vy_u1, vz_u0, vz_u1 }
    for (int idx = tid; idx < 64 * 64; idx += THREADS) {
        int r  = idx >> 6;
        int u  = idx & 63;
        int gr = min(row0 + r, n - 1);
        const float* rowp = in1 + (long)gr * 256;
        float s1 = rowp[u];
        float vx = rowp[64 + 3 * u + 0];
        float vy = rowp[64 + 3 * u + 1];
        float vz = rowp[64 + 3 * u + 2];
        float s2  = sc[r * 4 + 0];
        float v2x = sc[r * 4 + 1];
        float v2y = sc[r * 4 + 2];
        float v2z = sc[r * 4 + 3];
        float vvs = (vx * v2x + vy * v2y + vz * v2z) * INV_SQRT3;
        float* ap = A + r * 384 + (u >> 1) * 12 + (u & 1);
        ap[0]  = s1 * s2;
        ap[2]  = vvs;
        ap[4]  = s1;
        ap[6]  = vx;
        ap[8]  = vy;
        ap[10] = vz;
    }
    __syncthreads();

    // --- main loop: warp owns rows 4w..4w+3; lane owns cols (lane, lane+32) ---
    const int lane  = tid & 31;
    const int wrp   = tid >> 5;
    const int rbase = wrp * 4;

    // acc[r][k]: k = 2*type + half; types: 0=s, 1=sv, 2=vsx, 3=vsy, 4=vsz
    ull acc[4][10];
    #pragma unroll
    for (int r = 0; r < 4; r++)
        #pragma unroll
        for (int k = 0; k < 10; k++) acc[r][k] = 0ull;

    const ulonglong2* Bp = (const ulonglong2*)Wq;

    #pragma unroll 1
    for (int up = 0; up < 32; up++) {
        ulonglong2 q0l = Bp[0 * 1024 + up * 32 + lane];   // .x=ss2 .y=vv2 (col lo)
        ulonglong2 q1l = Bp[1 * 1024 + up * 32 + lane];   // .x=sv2 .y=vs2
        ulonglong2 q0h = Bp[2 * 1024 + up * 32 + lane];   // col hi
        ulonglong2 q1h = Bp[3 * 1024 + up * 32 + lane];
        #pragma unroll
        for (int r = 0; r < 4; r++) {
            const ulonglong2* ap =
                (const ulonglong2*)(A + (rbase + r) * 384 + up * 12);
            ulonglong2 a0 = ap[0];   // .x=s1s2  .y=vvs
            ulonglong2 a1 = ap[1];   // .x=s1    .y=vx
            ulonglong2 a2 = ap[2];   // .x=vy    .y=vz
            acc[r][0] = fma2(a0.x, q0l.x, acc[r][0]);
            acc[r][0] = fma2(a0.y, q0l.y, acc[r][0]);
            acc[r][2] = fma2(a1.x, q1l.x, acc[r][2]);
            acc[r][4] = fma2(a1.y, q1l.y, acc[r][4]);
            acc[r][6] = fma2(a2.x, q1l.y, acc[r][6]);
            acc[r][8] = fma2(a2.y, q1l.y, acc[r][8]);
            acc[r][1] = fma2(a0.x, q0h.x, acc[r][1]);
            acc[r][1] = fma2(a0.y, q0h.y, acc[r][1]);
            acc[r][3] = fma2(a1.x, q1h.x, acc[r][3]);
            acc[r][5] = fma2(a1.y, q1h.y, acc[r][5]);
            acc[r][7] = fma2(a2.x, q1h.y, acc[r][7]);
            acc[r][9] = fma2(a2.y, q1h.y, acc[r][9]);
        }
    }

    __syncthreads();   // all warps done reading A -> reuse as output staging

    // --- epilogue: combine and stage into smem [64 rows][256 cols] ---
    float* stile = smem;
    #pragma unroll
    for (int r = 0; r < 4; r++) {
        int lr = rbase + r;
        float s2  = sc[lr * 4 + 0];
        float v2x = sc[lr * 4 + 1];
        float v2y = sc[lr * 4 + 2];
        float v2z = sc[lr * 4 + 3];
        float* o = stile + lr * 256;
        #pragma unroll
        for (int j = 0; j < 2; j++) {
            int w = lane + 32 * j;
            float s  = red2(acc[r][0 + j]);
            float sv = red2(acc[r][2 + j]);
            float tx = red2(acc[r][4 + j]);
            float ty = red2(acc[r][6 + j]);
            float tz = red2(acc[r][8 + j]);
            o[w] = s + bsm[w];
            o[64 + 3 * w + 0] = sv * v2x + tx * s2;
            o[64 + 3 * w + 1] = sv * v2y + ty * s2;
            o[64 + 3 * w + 2] = sv * v2z + tz * s2;
        }
    }
    __syncthreads();

    // --- coalesced float4 store ---
    const float4* st4 = (const float4*)stile;
    float4* out4 = (float4*)(out + (long)row0 * 256);
    int rows_here = min(ROWS_PER_BLOCK, n - row0);
    int nfl4 = rows_here * 64;
    for (int idx = tid; idx < nfl4; idx += THREADS)
        out4[idx] = st4[idx];
}

extern "C" void kernel_launch(void* const* d_in, const int* in_sizes, int n_in,
                              void* d_out, int out_size) {
    const float* in1  = (const float*)d_in[0];
    const float* in2  = (const float*)d_in[1];
    const float* Wss  = (const float*)d_in[2];
    const float* Wvv  = (const float*)d_in[3];
    const float* Wsv  = (const float*)d_in[4];
    const float* Wvs  = (const float*)d_in[5];
    const float* bias = (const float*)d_in[6];
    float* out = (float*)d_out;

    int n = in_sizes[0] / 256;   // rows

    cudaFuncSetAttribute(o3tp_kernel, cudaFuncAttributeMaxDynamicSharedMemorySize, SMEM_BYTES);

    int blocks = (n + ROWS_PER_BLOCK - 1) / ROWS_PER_BLOCK;
    o3tp_kernel<<<blocks, THREADS, SMEM_BYTES>>>(in1, in2, Wss, Wvv, Wsv, Wvs, bias, out, n);
}